// round 17
// baseline (speedup 1.0000x reference)
#include <cuda_runtime.h>
#include <math.h>

#define NN 1024
#define H 128
#define THREADS 1024
#define NBLOCKS (NN / 8)

typedef unsigned long long u64;
#define ABSM 0x7FFFFFFF7FFFFFFFULL

// ---------------- f32x2 packed helpers ----------------
__device__ __forceinline__ u64 f2add(u64 a, u64 b) {
    u64 r; asm("add.rn.f32x2 %0,%1,%2;" : "=l"(r) : "l"(a), "l"(b)); return r;
}
__device__ __forceinline__ void f2fma(u64& d, u64 a, u64 b) {
    asm("fma.rn.f32x2 %0,%1,%2,%0;" : "+l"(d) : "l"(a), "l"(b));
}
__device__ __forceinline__ float2 f2un(u64 v) {
    float2 f; asm("mov.b64 {%0,%1},%2;" : "=f"(f.x), "=f"(f.y) : "l"(v)); return f;
}
__device__ __forceinline__ u64 f2dup(float a) {
    u64 r; asm("mov.b64 %0,{%1,%1};" : "=l"(r) : "f"(a)); return r;
}

// ---------------- device scratch ----------------
// kb2: [m2][j][4] = {k(2*m2), beta(2*m2), k(2*m2+1), beta(2*m2+1)}
// 64 real m2 rows + 4 pad rows for prefetch overrun
__device__ float g_kb2[(H / 2 + 4) * NN * 4];
__device__ float g_v[NN * H];              // v row-major
__device__ float g_B[NN];                  // sum_m beta

// ---------------- grid barrier state ----------------
__device__ unsigned bar_cnt;
__device__ volatile unsigned bar_gen;

// ---------------- smem layout (floats) ----------------
#define SM_QD   0        // 128*8 q [m][i]
#define SM_AD   1024     // 128*8 alpha
#define SM_SD   2048     // 128*2 dup sig
#define SM_XI   2304     // 16
#define SM_ASH  2320     // 8
#define SM_SMX  2328     // 32
#define SM_SSUM 2360     // 32
#define SM_DXS  2392     // 32*16
#define SM_WP2  2648     // 64 (per-warp A/B partials)
#define SM_SINV 2712     // 8 (per-row 1/sum)
#define SM_P    2720     // 8*1024 scores [i][j]  (phase-1 overlays here)
#define SM_AVP  10912    // 32*8*128 AV partials (phase-1 GEMV partials overlay)
#define SM_P2   43680    // 1024*8 transposed probs [j][i]
#define SMEM_FLOATS (SM_P2 + 8192)

// phase-1 overlays
#define PH_HS   SM_P             // 1024 floats (h rows)
#define PH_WS   (SM_P + 1024)    // 128
#define PH_XS   (SM_P + 1152)    // 16
#define PH_CP   (SM_P + 1168)    // 4
#define PH_CV   (SM_P + 1172)    // 1
// GEMV partials in AVP region, stride-9 padded: [seg*128+o]*9 + row
#define PH_PQ   SM_AVP                 // 4608
#define PH_PK   (SM_AVP + 4608)        // 4608
#define PH_PV   (SM_AVP + 9216)        // 4608

__global__ __launch_bounds__(THREADS, 1)
void fused_kernel(const float* __restrict__ h, const float* __restrict__ x,
                  const float* __restrict__ Wq, const float* __restrict__ bq,
                  const float* __restrict__ Wk, const float* __restrict__ bk,
                  const float* __restrict__ Wv, const float* __restrict__ bv,
                  const float* __restrict__ We1, const float* __restrict__ be1,
                  const float* __restrict__ We2, const float* __restrict__ be2,
                  const float* __restrict__ Wc, const float* __restrict__ bc,
                  float* __restrict__ out_h, float* __restrict__ out_x)
{
    extern __shared__ float sm[];
    float* Qd  = sm + SM_QD;
    float* Ad  = sm + SM_AD;
    float* Sd  = sm + SM_SD;
    float* XI  = sm + SM_XI;
    float* ASH = sm + SM_ASH;
    float* SMX = sm + SM_SMX;
    float* SSUM= sm + SM_SSUM;
    float* DXS = sm + SM_DXS;
    float* WP2 = sm + SM_WP2;
    float* SINV= sm + SM_SINV;
    float* P   = sm + SM_P;
    float* AVP = sm + SM_AVP;
    float* P2  = sm + SM_P2;
    float* hs  = sm + PH_HS;
    float* ws  = sm + PH_WS;
    float* xs2 = sm + PH_XS;
    float* cp  = sm + PH_CP;
    float* cv  = sm + PH_CV;

    int t = threadIdx.x;
    int i0 = blockIdx.x * 8;
    int r0 = i0;
    int w = t >> 5, l = t & 31;

    // ===================== PHASE 1 =========================================
    hs[t] = h[r0 * H + t];
    if (t < 16) { float xv = x[r0 * 2 + t]; xs2[t] = xv; XI[t] = xv; }
    __syncthreads();

    // ---- GEMV partials: seg = t>>8 owns m in [seg*32, seg*32+32) ----
    {
        int seg = t >> 8;
        int sub = t & 255;
        int o = sub & 127;
        int g = sub >> 7;           // row group: rows g*4..g*4+3
        int m0 = seg * 32;

        float aq[4] = {0.f, 0.f, 0.f, 0.f};
        float ak[4] = {0.f, 0.f, 0.f, 0.f};
        float av[4] = {0.f, 0.f, 0.f, 0.f};
#pragma unroll 4
        for (int mm = 0; mm < 32; ++mm) {
            int m = m0 + mm;
            float wq = Wq[m * H + o];
            float wk = Wk[m * H + o];
            float wv = Wv[m * H + o];
#pragma unroll
            for (int r = 0; r < 4; ++r) {
                float hm = hs[(g * 4 + r) * H + m];
                aq[r] = fmaf(hm, wq, aq[r]);
                ak[r] = fmaf(hm, wk, ak[r]);
                av[r] = fmaf(hm, wv, av[r]);
            }
        }
        int pb = (seg * 128 + o) * 9 + g * 4;
#pragma unroll
        for (int r = 0; r < 4; ++r) {
            sm[PH_PQ + pb + r] = aq[r];
            sm[PH_PK + pb + r] = ak[r];
            sm[PH_PV + pb + r] = av[r];
        }
    }

    // ---- w-fold: ws[m] = We2[m,:]@Wc (threads 0..255) ----
    if (t < 256) {
        int m = t >> 1, half = t & 1;
        const float* row = We2 + m * H + half * 64;
        const float* wc  = Wc + half * 64;
        float acc = 0.f;
#pragma unroll 16
        for (int o = 0; o < 64; ++o) acc = fmaf(row[o], wc[o], acc);
        acc += __shfl_xor_sync(0xffffffffu, acc, 1);
        if (!half) ws[m] = acc;
    }
    if (t < 128) {
        float p = be2[t] * Wc[t];
#pragma unroll
        for (int s = 16; s > 0; s >>= 1)
            p += __shfl_xor_sync(0xffffffffu, p, s);
        if (l == 0) cp[w] = p;
    }
    __syncthreads();
    if (t == 0) cv[0] = cp[0] + cp[1] + cp[2] + cp[3] + bc[0];
    if (t < 128) { float s = (ws[t] >= 0.f) ? 1.0f : -1.0f; Sd[2 * t] = s; Sd[2 * t + 1] = s; }

    // ---- reduce partials + alpha/beta: thread owns (row = t>>7, o = t&127) ----
    {
        int row = t >> 7;
        int o = t & 127;
        const float SCALE = 0.08838834764831845f;  // 1/sqrt(128)

        float q = bq[o], k = bk[o], v = bv[o];
#pragma unroll
        for (int seg = 0; seg < 4; ++seg) {
            int pb = (seg * 128 + o) * 9 + row;
            q += sm[PH_PQ + pb];
            k += sm[PH_PK + pb];
            v += sm[PH_PV + pb];
        }
        Qd[o * 8 + row] = q * SCALE;
        g_v[(r0 + row) * H + o] = v;

        float wo = ws[o];
        float u  = fmaf(xs2[row * 2], We1[o], xs2[row * 2 + 1] * We1[H + o]);
        float al = 0.5f * wo * (u + be1[o]);
        float be = -0.5f * wo * u;
        Ad[o * 8 + row] = al;
        // kb2 m-pair tiled layout
        *(float2*)&g_kb2[(o >> 1) * (NN * 4) + (r0 + row) * 4 + (o & 1) * 2] =
            make_float2(k, be);

        // warp = one row (32 o's): reduce alpha/beta
        float sA = al, sB = be;
#pragma unroll
        for (int s = 16; s > 0; s >>= 1) {
            sA += __shfl_xor_sync(0xffffffffu, sA, s);
            sB += __shfl_xor_sync(0xffffffffu, sB, s);
        }
        if (l == 0) { WP2[w * 2] = sA; WP2[w * 2 + 1] = sB; }
    }
    __syncthreads();
    if (t < 8) {
        int row = t;
        float A = 0.f, B = 0.f;
#pragma unroll
        for (int k2 = 0; k2 < 4; ++k2) {
            A += WP2[(row * 4 + k2) * 2];
            B += WP2[(row * 4 + k2) * 2 + 1];
        }
        ASH[row] = cv[0] + A;
        g_B[r0 + row] = B;
    }

    // ===================== GRID BARRIER ====================================
    __syncthreads();
    if (t == 0) {
        __threadfence();
        unsigned g = bar_gen;
        if (atomicAdd(&bar_cnt, 1) == (unsigned)(gridDim.x - 1)) {
            bar_cnt = 0;
            __threadfence();
            bar_gen = g + 1;
        } else {
            while (bar_gen == g) { __nanosleep(64); }
            __threadfence();
        }
    }
    __syncthreads();

    // ===================== PHASE 2: fused attention ========================
    // Fused score + gate m-loop (thread owns j = t); kb2 LDG.128 serves 2 m.
    u64 acc[4], ga[4];
#pragma unroll
    for (int ip = 0; ip < 4; ++ip) { acc[ip] = 0ull; ga[ip] = 0ull; }
    {
        const float4* kbp = (const float4*)g_kb2 + t;   // stride NN per m2
        float4 bufA[2], bufB[2];
        bufA[0] = kbp[0 * NN];
        bufA[1] = kbp[1 * NN];

#define MPAIR_COMPUTE(m2v, kb4)                                              \
        {                                                                    \
            ulonglong2 sd2 = *(const ulonglong2*)(Sd + 4 * (m2v));           \
            {                                                                \
                int m = 2 * (m2v);                                           \
                u64 kd = f2dup((kb4).x);                                     \
                u64 bd = f2dup((kb4).y);                                     \
                ulonglong2 qA = *(const ulonglong2*)(Qd + m * 8);            \
                ulonglong2 qB = *(const ulonglong2*)(Qd + m * 8 + 4);        \
                ulonglong2 aA = *(const ulonglong2*)(Ad + m * 8);            \
                ulonglong2 aB = *(const ulonglong2*)(Ad + m * 8 + 4);        \
                f2fma(acc[0], qA.x, kd);                                     \
                f2fma(acc[1], qA.y, kd);                                     \
                f2fma(acc[2], qB.x, kd);                                     \
                f2fma(acc[3], qB.y, kd);                                     \
                u64 z;                                                       \
                z = f2add(aA.x, bd) & ABSM; f2fma(ga[0], z, sd2.x);          \
                z = f2add(aA.y, bd) & ABSM; f2fma(ga[1], z, sd2.x);          \
                z = f2add(aB.x, bd) & ABSM; f2fma(ga[2], z, sd2.x);          \
                z = f2add(aB.y, bd) & ABSM; f2fma(ga[3], z, sd2.x);          \
            }                                                                \
            {                                                                \
                int m = 2 * (m2v) + 1;                                       \
                u64 kd = f2dup((kb4).z);                                     \
                u64 bd = f2dup((kb4).w);                                     \
                ulonglong2 qA = *(const ulonglong2*)(Qd + m * 8);            \
                ulonglong2 qB = *(const ulonglong2*)(Qd + m * 8 + 4);        \
                ulonglong2 aA = *(const ulonglong2*)(Ad + m * 8);            \
                ulonglong2 aB = *(const ulonglong2*)(Ad + m * 8 + 4);        \
                f2fma(acc[0], qA.x, kd);                                     \
                f2fma(acc[1], qA.y, kd);                                     \
                f2fma(acc[2], qB.x, kd);                                     \
                f2fma(acc[3], qB.y, kd);                                     \
                u64 z;                                                       \
                z = f2add(aA.x, bd) & ABSM; f2fma(ga[0], z, sd2.y);          \
                z = f2add(aA.y, bd) & ABSM; f2fma(ga[1], z, sd2.y);          \
                z = f2add(aB.x, bd) & ABSM; f2fma(ga[2], z, sd2.y);          \
                z = f2add(aB.y, bd) & ABSM; f2fma(ga[3], z, sd2.y);          \
            }                                                                \
        }

#pragma unroll 1
        for (int mg = 0; mg < 16; ++mg) {
            int b2 = mg * 4;
            bufB[0] = kbp[(b2 + 2) * NN];
            bufB[1] = kbp[(b2 + 3) * NN];
            MPAIR_COMPUTE(b2,     bufA[0]);
            MPAIR_COMPUTE(b2 + 1, bufA[1]);
            bufA[0] = kbp[(b2 + 4) * NN];   // pad rows cover the tail
            bufA[1] = kbp[(b2 + 5) * NN];
            MPAIR_COMPUTE(b2 + 2, bufB[0]);
            MPAIR_COMPUTE(b2 + 3, bufB[1]);
        }
#undef MPAIR_COMPUTE
    }
#pragma unroll
    for (int ip = 0; ip < 4; ++ip) {
        float2 f = f2un(acc[ip]);
        P[(2 * ip) * NN + t]     = f.x;
        P[(2 * ip + 1) * NN + t] = f.y;
    }
    __syncthreads();

    // Softmax: 4 warps per row (quarters); P keeps UNSCALED exp, SINV holds 1/sum
    {
        int row = w >> 2, qt = w & 3;
        float* prow = P + row * NN + qt * 256;
        float mx = -1e30f;
        for (int j = l; j < 256; j += 32) mx = fmaxf(mx, prow[j]);
#pragma unroll
        for (int s = 16; s > 0; s >>= 1)
            mx = fmaxf(mx, __shfl_xor_sync(0xffffffffu, mx, s));
        if (l == 0) SMX[w] = mx;
        __syncthreads();
        float M = fmaxf(fmaxf(SMX[row * 4], SMX[row * 4 + 1]),
                        fmaxf(SMX[row * 4 + 2], SMX[row * 4 + 3]));
        float sum = 0.f;
        for (int j = l; j < 256; j += 32) {
            float e = __expf(prow[j] - M);
            prow[j] = e;
            sum += e;
        }
#pragma unroll
        for (int s = 16; s > 0; s >>= 1)
            sum += __shfl_xor_sync(0xffffffffu, sum, s);
        if (l == 0) SSUM[w] = sum;
    }
    __syncthreads();
    if (t < 8)
        SINV[t] = 1.f / (SSUM[t * 4] + SSUM[t * 4 + 1]
                       + SSUM[t * 4 + 2] + SSUM[t * 4 + 3]);
    __syncthreads();

    // Gate combine: delta_x (thread owns j = t); normalize on the fly
    {
        float4 si0 = *(const float4*)SINV;
        float4 si1 = *(const float4*)(SINV + 4);
        float sinv[8] = {si0.x, si0.y, si0.z, si0.w, si1.x, si1.y, si1.z, si1.w};
        float pv[8];
#pragma unroll
        for (int i = 0; i < 8; ++i) pv[i] = P[i * NN + t] * sinv[i];
        *(float4*)&P2[t * 8]     = make_float4(pv[0], pv[1], pv[2], pv[3]);
        *(float4*)&P2[t * 8 + 4] = make_float4(pv[4], pv[5], pv[6], pv[7]);
        __syncwarp();

        float Bj = g_B[t];
        float2 xj = *(const float2*)(x + 2 * t);
        float dxv[8], dyv[8];
#pragma unroll
        for (int ip = 0; ip < 4; ++ip) {
            float2 g2 = f2un(ga[ip]);
            int ia = 2 * ip, ib = 2 * ip + 1;
            float G0 = ASH[ia] + Bj + g2.x;
            float G1 = ASH[ib] + Bj + g2.y;
            float pg0 = pv[ia] * G0;
            float pg1 = pv[ib] * G1;
            dxv[ia] = pg0 * (XI[2 * ia]     - xj.x);
            dyv[ia] = pg0 * (XI[2 * ia + 1] - xj.y);
            dxv[ib] = pg1 * (XI[2 * ib]     - xj.x);
            dyv[ib] = pg1 * (XI[2 * ib + 1] - xj.y);
        }
#pragma unroll
        for (int s = 16; s > 0; s >>= 1) {
#pragma unroll
            for (int i = 0; i < 8; ++i) {
                dxv[i] += __shfl_xor_sync(0xffffffffu, dxv[i], s);
                dyv[i] += __shfl_xor_sync(0xffffffffu, dyv[i], s);
            }
        }
        if (l == 0) {
#pragma unroll
            for (int i = 0; i < 8; ++i) {
                DXS[w * 16 + 2 * i]     = dxv[i];
                DXS[w * 16 + 2 * i + 1] = dyv[i];
            }
        }
    }
    __syncthreads();   // P2 fully written (cross-warp consumption in AV)

    // AV: warp owns 32 j's, lane owns 4 cols
    {
        u64 av[8][2];
#pragma unroll
        for (int i = 0; i < 8; ++i) { av[i][0] = 0ull; av[i][1] = 0ull; }
        int c0 = l << 2;
        int jbase = w << 5;
#pragma unroll 2
        for (int jj = 0; jj < 32; ++jj) {
            int j = jbase + jj;
            ulonglong2 v2 = *(const ulonglong2*)(g_v + j * H + c0);
            float4 pa = *(const float4*)&P2[j * 8];
            float4 pb = *(const float4*)&P2[j * 8 + 4];
            f2fma(av[0][0], f2dup(pa.x), v2.x); f2fma(av[0][1], f2dup(pa.x), v2.y);
            f2fma(av[1][0], f2dup(pa.y), v2.x); f2fma(av[1][1], f2dup(pa.y), v2.y);
            f2fma(av[2][0], f2dup(pa.z), v2.x); f2fma(av[2][1], f2dup(pa.z), v2.y);
            f2fma(av[3][0], f2dup(pa.w), v2.x); f2fma(av[3][1], f2dup(pa.w), v2.y);
            f2fma(av[4][0], f2dup(pb.x), v2.x); f2fma(av[4][1], f2dup(pb.x), v2.y);
            f2fma(av[5][0], f2dup(pb.y), v2.x); f2fma(av[5][1], f2dup(pb.y), v2.y);
            f2fma(av[6][0], f2dup(pb.z), v2.x); f2fma(av[6][1], f2dup(pb.z), v2.y);
            f2fma(av[7][0], f2dup(pb.w), v2.x); f2fma(av[7][1], f2dup(pb.w), v2.y);
        }
#pragma unroll
        for (int i = 0; i < 8; ++i) {
            float2 a = f2un(av[i][0]);
            float2 b = f2un(av[i][1]);
            *(float4*)&AVP[(w * 8 + i) * 128 + c0] = make_float4(a.x, a.y, b.x, b.y);
        }
    }
    __syncthreads();

    // Final reduce + epilogue
    {
        int i = t >> 7, c = t & 127;
        float s = 0.f;
#pragma unroll
        for (int w2 = 0; w2 < 32; ++w2)
            s += AVP[(w2 * 8 + i) * 128 + c];
        out_h[(i0 + i) * H + c] = h[(i0 + i) * H + c] + s;
    }
    if (t < 16) {
        int i = t >> 1, d = t & 1;
        float s = 0.f;
#pragma unroll
        for (int w2 = 0; w2 < 32; ++w2) s += DXS[w2 * 16 + 2 * i + d];
        out_x[(i0 + i) * 2 + d] = x[(i0 + i) * 2 + d] + s;
    }
}

// ---------------------------------------------------------------------------
extern "C" void kernel_launch(void* const* d_in, const int* in_sizes, int n_in,
                              void* d_out, int out_size)
{
    const float* h   = (const float*)d_in[0];
    const float* x   = (const float*)d_in[1];
    const float* Wq  = (const float*)d_in[3];
    const float* bq  = (const float*)d_in[4];
    const float* Wk  = (const float*)d_in[5];
    const float* bk  = (const float*)d_in[6];
    const float* Wv  = (const float*)d_in[7];
    const float* bv  = (const float*)d_in[8];
    const float* We1 = (const float*)d_in[9];
    const float* be1 = (const float*)d_in[10];
    const float* We2 = (const float*)d_in[11];
    const float* be2 = (const float*)d_in[12];
    const float* Wc  = (const float*)d_in[13];
    const float* bc  = (const float*)d_in[14];

    float* out   = (float*)d_out;
    float* out_h = out;
    float* out_x = out + NN * H;

    size_t smem_bytes = (size_t)SMEM_FLOATS * sizeof(float);
    cudaFuncSetAttribute(fused_kernel,
                         cudaFuncAttributeMaxDynamicSharedMemorySize,
                         (int)smem_bytes);

    fused_kernel<<<NBLOCKS, THREADS, smem_bytes>>>(
        h, x, Wq, bq, Wk, bk, Wv, bv, We1, be1, We2, be2, Wc, bc,
        out_h, out_x);
}